// round 4
// baseline (speedup 1.0000x reference)
#include <cuda_runtime.h>
#include <cstdint>
#include <math.h>

// ---------------------------------------------------------------------------
// Threefry-2x32 (exact JAX implementation: jax/_src/prng.py)
// ---------------------------------------------------------------------------
__host__ __device__ __forceinline__ void threefry2x32(
    unsigned k0, unsigned k1, unsigned x0, unsigned x1,
    unsigned &o0, unsigned &o1)
{
    const unsigned ks2 = k0 ^ k1 ^ 0x1BD11BDAu;
    unsigned a = x0 + k0, b = x1 + k1;
#define TF_ROT(v,d) (((v)<<(d))|((v)>>(32-(d))))
#define TF_R4(r0_,r1_,r2_,r3_) \
    a+=b; b=TF_ROT(b,r0_); b^=a; \
    a+=b; b=TF_ROT(b,r1_); b^=a; \
    a+=b; b=TF_ROT(b,r2_); b^=a; \
    a+=b; b=TF_ROT(b,r3_); b^=a;
    TF_R4(13,15,26, 6);  a+=k1;  b+=ks2+1u;
    TF_R4(17,29,16,24);  a+=ks2; b+=k0 +2u;
    TF_R4(13,15,26, 6);  a+=k0;  b+=k1 +3u;
    TF_R4(17,29,16,24);  a+=k1;  b+=ks2+4u;
    TF_R4(13,15,26, 6);  a+=ks2; b+=k0 +5u;
    o0 = a; o1 = b;
#undef TF_R4
#undef TF_ROT
}

// ---------------------------------------------------------------------------
// Packed fp32x2 helpers (sm_103a FFMA2 — 2x FFMA throughput)
// ---------------------------------------------------------------------------
__device__ __forceinline__ unsigned long long pack_dup(float a) {
    unsigned long long r;
    asm("mov.b64 %0, {%1, %1};" : "=l"(r) : "f"(a));
    return r;
}
__device__ __forceinline__ unsigned long long fma2(
    unsigned long long a, unsigned long long b, unsigned long long c) {
    unsigned long long d;
    asm("fma.rn.f32x2 %0, %1, %2, %3;" : "=l"(d) : "l"(a), "l"(b), "l"(c));
    return d;
}

// ---------------------------------------------------------------------------
// GEMM: out[T,128] = H[T,D] @ W[D,128], fp32 accurate.
// Tile 128x128xBK16, 256 threads, 8x8 per thread, FFMA2 over expert pairs.
// ---------------------------------------------------------------------------
__global__ __launch_bounds__(256, 1)
void gemm128(const float* __restrict__ H, const float* __restrict__ W,
             float* __restrict__ out, int D)
{
    __shared__ float As[16][132];   // transposed h tile (padded rows)
    __shared__ float Bs[16][128];

    const int tid = threadIdx.x;
    const int bm  = blockIdx.x * 128;

    // compute-thread mapping: 16x16 grid, 4+4 split in each dim
    const int trow = tid >> 4;          // 0..15
    const int tcol = tid & 15;          // 0..15
    const int m0   = trow * 4;
    const int n0   = tcol * 4;

    // load mapping
    const int lrow = tid >> 2;          // 0..63 (A rows; +64 for second half)
    const int lkq  = (tid & 3) * 4;     // k offset within BK
    const int bkr  = tid >> 5;          // 0..7  (B k rows; +8 second half)
    const int bc   = (tid & 31) * 4;    // B column

    const float* hPtr = H + (size_t)(bm + lrow) * (size_t)D + lkq;
    const float* wPtr = W + bkr * 128 + bc;

    unsigned long long acc[8][4];
#pragma unroll
    for (int i = 0; i < 8; i++)
#pragma unroll
        for (int j = 0; j < 4; j++) acc[i][j] = 0ull;

    const int nIter = D / 16;

    // preload tile 0
    float4 ra0 = *(const float4*)(hPtr);
    float4 ra1 = *(const float4*)(hPtr + (size_t)64 * D);
    float4 rb0 = *(const float4*)(wPtr);
    float4 rb1 = *(const float4*)(wPtr + 8 * 128);

    for (int it = 0; it < nIter; ++it) {
        // store current tile to smem (A transposed)
        As[lkq + 0][lrow]      = ra0.x;
        As[lkq + 1][lrow]      = ra0.y;
        As[lkq + 2][lrow]      = ra0.z;
        As[lkq + 3][lrow]      = ra0.w;
        As[lkq + 0][lrow + 64] = ra1.x;
        As[lkq + 1][lrow + 64] = ra1.y;
        As[lkq + 2][lrow + 64] = ra1.z;
        As[lkq + 3][lrow + 64] = ra1.w;
        *(float4*)&Bs[bkr    ][bc] = rb0;
        *(float4*)&Bs[bkr + 8][bc] = rb1;
        __syncthreads();

        // prefetch next tile into registers (hidden under compute)
        if (it + 1 < nIter) {
            const float* hp = hPtr + (size_t)(it + 1) * 16;
            ra0 = *(const float4*)(hp);
            ra1 = *(const float4*)(hp + (size_t)64 * D);
            const float* wp = wPtr + (size_t)(it + 1) * 16 * 128;
            rb0 = *(const float4*)(wp);
            rb1 = *(const float4*)(wp + 8 * 128);
        }

#pragma unroll
        for (int k = 0; k < 16; ++k) {
            float4 a0 = *(const float4*)&As[k][m0];
            float4 a1 = *(const float4*)&As[k][m0 + 64];
            unsigned long long bp[4];
            bp[0] = *(const unsigned long long*)&Bs[k][n0];
            bp[1] = *(const unsigned long long*)&Bs[k][n0 + 2];
            bp[2] = *(const unsigned long long*)&Bs[k][n0 + 64];
            bp[3] = *(const unsigned long long*)&Bs[k][n0 + 66];
            unsigned long long ap[8];
            ap[0] = pack_dup(a0.x); ap[1] = pack_dup(a0.y);
            ap[2] = pack_dup(a0.z); ap[3] = pack_dup(a0.w);
            ap[4] = pack_dup(a1.x); ap[5] = pack_dup(a1.y);
            ap[6] = pack_dup(a1.z); ap[7] = pack_dup(a1.w);
#pragma unroll
            for (int mi = 0; mi < 8; ++mi)
#pragma unroll
                for (int pj = 0; pj < 4; ++pj)
                    acc[mi][pj] = fma2(ap[mi], bp[pj], acc[mi][pj]);
        }
        __syncthreads();
    }

    // writeback (8B stores of fp32 pairs; n even -> aligned)
#pragma unroll
    for (int mi = 0; mi < 8; ++mi) {
        const int m = bm + m0 + (mi & 3) + ((mi >> 2) << 6);
#pragma unroll
        for (int pj = 0; pj < 4; ++pj) {
            const int n = n0 + ((pj & 1) << 1) + ((pj >> 1) << 6);
            *(unsigned long long*)&out[(size_t)m * 128 + n] = acc[mi][pj];
        }
    }
}

// ---------------------------------------------------------------------------
// Epilogue: one CTA per token (128 threads = E).
// gumbel (threefry, partitionable stream), logits_sel, top-8, softmax, renorm
// ---------------------------------------------------------------------------
__global__ __launch_bounds__(128)
void router_epilogue(const float* __restrict__ logits,
                     const int* __restrict__ tmask,   // 4-byte bool (int32/f32)
                     float* __restrict__ out_mask,
                     float* __restrict__ out_probs,
                     float* __restrict__ out_lsel,
                     unsigned fk0, unsigned fk1)
{
    const int t = blockIdx.x;
    const int e = threadIdx.x;
    const unsigned idx = (unsigned)t * 128u + (unsigned)e;

    const float lc = logits[idx];

    // --- JAX-exact gumbel noise (jax_threefry_partitionable=True path) ----
    // counts = (flat_idx >> 32, flat_idx & 0xffffffff); bits = o0 ^ o1
    unsigned o0, o1;
    threefry2x32(fk0, fk1, 0u, idx, o0, o1);
    const unsigned bits = o0 ^ o1;
    float f = __uint_as_float((bits >> 9) | 0x3f800000u) - 1.0f;
    const float minv = 1e-6f;
    const float maxv = (float)(1.0 - 1e-6);
    float u = f * (maxv - minv) + minv;
    u = fmaxf(minv, u);
    const float g = -logf(-logf(u));

    const bool tm  = (tmask[t] != 0);
    const float ls  = lc + g;                      // tau=1, t_sel=1
    const float lsm = tm ? ls : -INFINITY;

    __shared__ float s_val[128];
    __shared__ float s_red[4];
    __shared__ int   s_idx[4];
    __shared__ int   s_arg;
    __shared__ float s_b;

    s_val[e] = lsm;
    __syncthreads();

    // --- top-8 via iterative block-argmax (ties -> lowest index) ----------
    bool selected = false;
#pragma unroll 1
    for (int it = 0; it < 8; ++it) {
        float v = s_val[e];
        int   bi = e;
#pragma unroll
        for (int off = 16; off; off >>= 1) {
            float ov = __shfl_down_sync(0xffffffffu, v, off);
            int   oi = __shfl_down_sync(0xffffffffu, bi, off);
            if (ov > v || (ov == v && oi < bi)) { v = ov; bi = oi; }
        }
        if ((e & 31) == 0) { s_red[e >> 5] = v; s_idx[e >> 5] = bi; }
        __syncthreads();
        if (e == 0) {
            float bv = s_red[0]; int bb = s_idx[0];
#pragma unroll
            for (int w = 1; w < 4; ++w)
                if (s_red[w] > bv || (s_red[w] == bv && s_idx[w] < bb)) {
                    bv = s_red[w]; bb = s_idx[w];
                }
            s_arg = bb;
        }
        __syncthreads();
        if (e == s_arg) { selected = true; s_val[e] = -INFINITY; }
        __syncthreads();
    }

    // --- softmax over clean logits ----------------------------------------
    float v = lc;
#pragma unroll
    for (int off = 16; off; off >>= 1)
        v = fmaxf(v, __shfl_down_sync(0xffffffffu, v, off));
    if ((e & 31) == 0) s_red[e >> 5] = v;
    __syncthreads();
    if (e == 0) s_b = fmaxf(fmaxf(s_red[0], s_red[1]), fmaxf(s_red[2], s_red[3]));
    __syncthreads();
    const float mx = s_b;

    float p = expf(lc - mx);
    v = p;
#pragma unroll
    for (int off = 16; off; off >>= 1)
        v += __shfl_down_sync(0xffffffffu, v, off);
    if ((e & 31) == 0) s_red[e >> 5] = v;
    __syncthreads();
    if (e == 0) s_b = (s_red[0] + s_red[1]) + (s_red[2] + s_red[3]);
    __syncthreads();
    p = p / s_b;
    if (!tm) p = 0.0f;

    // --- masked renorm -----------------------------------------------------
    float mp = selected ? p : 0.0f;
    v = mp;
#pragma unroll
    for (int off = 16; off; off >>= 1)
        v += __shfl_down_sync(0xffffffffu, v, off);
    if ((e & 31) == 0) s_red[e >> 5] = v;
    __syncthreads();
    if (e == 0) s_b = (s_red[0] + s_red[1]) + (s_red[2] + s_red[3]);
    __syncthreads();
    const float den  = fmaxf(s_b, 1e-9f);
    float pout = mp / den;
    if (!tm) pout = 0.0f;

    out_mask [idx] = (selected && tm) ? 1.0f : 0.0f;
    out_probs[idx] = pout;
    out_lsel [idx] = lsm;
}

// ---------------------------------------------------------------------------
// launch
// ---------------------------------------------------------------------------
extern "C" void kernel_launch(void* const* d_in, const int* in_sizes, int n_in,
                              void* d_out, int out_size)
{
    const float* H  = (const float*)d_in[0];
    const float* W  = (const float*)d_in[1];
    const int*   tm = (const int*)d_in[2];     // bool promoted to 4-byte

    const int T = in_sizes[2];                 // 16384
    const int D = in_sizes[0] / T;             // 4096

    float* outF      = (float*)d_out;
    const unsigned TE = (unsigned)T * 128u;
    float* out_mask  = outF;
    float* out_probs = outF + TE;
    float* out_clean = outF + 2u * TE;
    float* out_sel   = outF + 3u * TE;

    gemm128<<<T / 128, 256>>>(H, W, out_clean, D);

    // folded key: fold_in(key(7), 1) = threefry([0,7], [0,1])
    unsigned fk0, fk1;
    threefry2x32(0u, 7u, 0u, 1u, fk0, fk1);

    router_epilogue<<<T, 128>>>(out_clean, tm, out_mask, out_probs, out_sel,
                                fk0, fk1);
}